// round 1
// baseline (speedup 1.0000x reference)
#include <cuda_runtime.h>
#include <math.h>

// Problem constants (fixed by the dataset)
#define NN   50000
#define EE   800000
#define DIN  64
#define DH   128
#define DOUT 10
#define EPS  1e-8f

// ---------------- scratch (static __device__ — no allocation) ----------------
__device__ int   g_degi[NN];
__device__ float g_deg[NN];
__device__ int   g_rowptr[NN + 1];
__device__ int   g_cursor[NN];
__device__ int   g_csrsrc[EE];
__device__ float g_agg0[NN * DIN];    // 12.8 MB
__device__ float g_h1[NN * DH];       // 25.6 MB
__device__ float g_s[NN * DOUT];
__device__ float g_t[NN * DOUT];
__device__ float g_agg1[NN * DOUT];

// ---------------- CSR build ----------------
__global__ void zero_deg_kernel() {
    int i = blockIdx.x * blockDim.x + threadIdx.x;
    if (i < NN) g_degi[i] = 0;
}

__global__ void count_kernel(const int* __restrict__ dst) {
    int e = blockIdx.x * blockDim.x + threadIdx.x;
    if (e < EE) atomicAdd(&g_degi[dst[e]], 1);
}

// single-block scan over 50000 degrees
__global__ void scan_kernel() {
    __shared__ int warp_sums[32];
    const int T = 1024;
    int tid = threadIdx.x;
    int per = (NN + T - 1) / T;             // 49
    int start = tid * per;
    int end = start + per; if (end > NN) end = NN;
    int local = 0;
    if (start < NN)
        for (int i = start; i < end; i++) local += g_degi[i];

    int lane = tid & 31, wid = tid >> 5;
    int v = local;
    #pragma unroll
    for (int o = 1; o < 32; o <<= 1) {
        int u = __shfl_up_sync(0xFFFFFFFFu, v, o);
        if (lane >= o) v += u;
    }
    if (lane == 31) warp_sums[wid] = v;
    __syncthreads();
    if (wid == 0) {
        int w = warp_sums[lane];
        #pragma unroll
        for (int o = 1; o < 32; o <<= 1) {
            int u = __shfl_up_sync(0xFFFFFFFFu, w, o);
            if (lane >= o) w += u;
        }
        warp_sums[lane] = w;
    }
    __syncthreads();
    int excl = v - local + (wid > 0 ? warp_sums[wid - 1] : 0);
    if (start < NN) {
        int run = excl;
        for (int i = start; i < end; i++) {
            g_rowptr[i] = run;
            g_cursor[i] = run;
            g_deg[i] = (float)g_degi[i];
            run += g_degi[i];
        }
    }
    if (tid == 0) g_rowptr[NN] = warp_sums[31];
}

__global__ void fill_kernel(const int* __restrict__ src, const int* __restrict__ dst) {
    int e = blockIdx.x * blockDim.x + threadIdx.x;
    if (e < EE) {
        int d = dst[e];
        int p = atomicAdd(&g_cursor[d], 1);
        g_csrsrc[p] = src[e];
    }
}

// ---------------- layer 0: aggregate raw x (64 feats), warp per node ----------------
__global__ void agg0_kernel(const float* __restrict__ x) {
    int node = blockIdx.x * (blockDim.x >> 5) + (threadIdx.x >> 5);
    if (node >= NN) return;
    int lane = threadIdx.x & 31;
    int beg = g_rowptr[node], end = g_rowptr[node + 1];
    float ax = 0.f, ay = 0.f;
    for (int j = beg; j < end; j++) {
        int s = g_csrsrc[j];
        float2 v = *(const float2*)(x + (size_t)s * DIN + lane * 2);
        ax += v.x; ay += v.y;
    }
    float2 o; o.x = ax; o.y = ay;
    *(float2*)(g_agg0 + (size_t)node * DIN + lane * 2) = o;
}

// ---------------- layer 0 transform: block = node, 128 threads ----------------
__global__ void __launch_bounds__(128) layer0_kernel(
    const float* __restrict__ x,
    const float* __restrict__ Ws,   // (65,128)
    const float* __restrict__ Wn)   // (65,128)
{
    __shared__ float sh_self[DIN + 1];
    __shared__ float sh_neigh[DIN + 1];
    __shared__ float red[4];
    int node = blockIdx.x;
    int tid = threadIdx.x;
    float degv = g_deg[node];
    float inv = 1.f / fmaxf(degv, 1.f);
    if (tid < DIN) {
        sh_self[tid]  = x[(size_t)node * DIN + tid];
        sh_neigh[tid] = g_agg0[(size_t)node * DIN + tid] * inv;
    }
    if (tid == DIN) {
        sh_self[DIN]  = 1.f;
        sh_neigh[DIN] = (degv > 0.f) ? 1.f : 0.f;
    }
    __syncthreads();
    float acc = 0.f;
    #pragma unroll 13
    for (int k = 0; k < DIN + 1; k++) {
        acc += sh_self[k]  * Ws[k * DH + tid];
        acc += sh_neigh[k] * Wn[k * DH + tid];
    }
    float sq = acc * acc;
    #pragma unroll
    for (int o = 16; o > 0; o >>= 1) sq += __shfl_xor_sync(0xFFFFFFFFu, sq, o);
    if ((tid & 31) == 0) red[tid >> 5] = sq;
    __syncthreads();
    float tot = red[0] + red[1] + red[2] + red[3];
    float o = acc / (sqrtf(tot) + EPS);
    g_h1[(size_t)node * DH + tid] = fmaxf(o, 0.f);   // relu
}

// ---------------- layer 1 projections: s = h@Ws1[:128] + Ws1[128], t = h@Wn1[:128] ----------------
__global__ void proj1_kernel(const float* __restrict__ Ws1,  // (129,10)
                             const float* __restrict__ Wn1)  // (129,10)
{
    int idx = blockIdx.x * blockDim.x + threadIdx.x;
    if (idx >= NN * DOUT) return;
    int node = idx / DOUT;
    int j = idx - node * DOUT;
    const float* h = g_h1 + (size_t)node * DH;
    float ss = Ws1[DH * DOUT + j];     // homogeneous (ones) row of W_self1
    float tt = 0.f;
    #pragma unroll 8
    for (int k = 0; k < DH; k++) {
        float hv = h[k];
        ss += hv * Ws1[k * DOUT + j];
        tt += hv * Wn1[k * DOUT + j];
    }
    g_s[idx] = ss;
    g_t[idx] = tt;
}

// ---------------- layer 1 aggregation in output space (10 feats) ----------------
__global__ void agg1_kernel() {
    int idx = blockIdx.x * blockDim.x + threadIdx.x;
    if (idx >= NN * DOUT) return;
    int node = idx / DOUT;
    int j = idx - node * DOUT;
    int beg = g_rowptr[node], end = g_rowptr[node + 1];
    float acc = 0.f;
    for (int p = beg; p < end; p++) {
        int s = g_csrsrc[p];
        acc += g_t[s * DOUT + j];
    }
    g_agg1[idx] = acc;
}

// ---------------- final: combine, projective norm, log-softmax ----------------
__global__ void final_kernel(const float* __restrict__ Wn1, float* __restrict__ out) {
    int node = blockIdx.x * blockDim.x + threadIdx.x;
    if (node >= NN) return;
    float degv = g_deg[node];
    float inv = 1.f / fmaxf(degv, 1.f);
    float ind = (degv > 0.f) ? 1.f : 0.f;
    float v[DOUT];
    float nrm = 0.f;
    #pragma unroll
    for (int j = 0; j < DOUT; j++) {
        float z = g_s[node * DOUT + j]
                + g_agg1[node * DOUT + j] * inv
                + ind * Wn1[DH * DOUT + j];
        v[j] = z;
        nrm += z * z;
    }
    float rinv = 1.f / (sqrtf(nrm) + EPS);
    float mx = -1e30f;
    #pragma unroll
    for (int j = 0; j < DOUT; j++) { v[j] *= rinv; mx = fmaxf(mx, v[j]); }
    float se = 0.f;
    #pragma unroll
    for (int j = 0; j < DOUT; j++) se += __expf(v[j] - mx);
    float lse = mx + logf(se);
    #pragma unroll
    for (int j = 0; j < DOUT; j++) out[node * DOUT + j] = v[j] - lse;
}

// ---------------- launch ----------------
extern "C" void kernel_launch(void* const* d_in, const int* in_sizes, int n_in,
                              void* d_out, int out_size) {
    const float* x   = (const float*)d_in[0];
    const int*   ei  = (const int*)d_in[1];      // (2, E): src row then dst row
    const float* Ws0 = (const float*)d_in[2];    // (65,128)
    const float* Wn0 = (const float*)d_in[3];    // (65,128)
    const float* Ws1 = (const float*)d_in[4];    // (129,10)
    const float* Wn1 = (const float*)d_in[5];    // (129,10)
    float* out = (float*)d_out;

    const int* src = ei;
    const int* dst = ei + EE;

    // CSR build
    zero_deg_kernel<<<(NN + 255) / 256, 256>>>();
    count_kernel<<<(EE + 255) / 256, 256>>>(dst);
    scan_kernel<<<1, 1024>>>();
    fill_kernel<<<(EE + 255) / 256, 256>>>(src, dst);

    // layer 0
    agg0_kernel<<<(NN * 32 + 255) / 256, 256>>>(x);
    layer0_kernel<<<NN, 128>>>(x, Ws0, Wn0);

    // layer 1 (aggregate in 10-dim output space)
    proj1_kernel<<<(NN * DOUT + 255) / 256, 256>>>(Ws1, Wn1);
    agg1_kernel<<<(NN * DOUT + 255) / 256, 256>>>();
    final_kernel<<<(NN + 255) / 256, 256>>>(Wn1, out);
}